// round 3
// baseline (speedup 1.0000x reference)
#include <cuda_runtime.h>

// Problem: shape (8,16,6,256,256) -> rows = 768, row_len = 65536.
#define ROW_LEN    65536
#define SEGS       8                     // segments per row (load balance)
#define SEG_LEN    (ROW_LEN / SEGS)      // 8192 elements
#define SEG_LEN4   (SEG_LEN / 4)         // 2048 float4
#define THREADS    256                   // 8 float4 per thread per segment
#define MAX_ROWS   4096

// Device-global scratch (no allocations allowed). Zero-init at load;
// counters are reset in-kernel so graph replays see a clean state.
__device__ float        g_part[MAX_ROWS * SEGS * 5];  // per-segment partial moments
__device__ unsigned int g_row_cnt[MAX_ROWS];          // segments-done per row
__device__ float        g_row_r[MAX_ROWS];            // per-row r
__device__ unsigned int g_done_rows = 0;              // rows fully combined

__global__ __launch_bounds__(THREADS, 1)
void fused_loss_kernel(const float* __restrict__ X, const float* __restrict__ Y,
                       float* __restrict__ out, int rows) {
    const int row = blockIdx.x >> 3;          // / SEGS
    const int seg = blockIdx.x & (SEGS - 1);
    const size_t base4 = (size_t)row * (ROW_LEN / 4) + (size_t)seg * SEG_LEN4;
    const float4* __restrict__ x4 = reinterpret_cast<const float4*>(X) + base4;
    const float4* __restrict__ y4 = reinterpret_cast<const float4*>(Y) + base4;

    float sx = 0.f, sy = 0.f, sxx = 0.f, syy = 0.f, sxy = 0.f;

    // 2048 float4 / 256 threads = 8 iterations.
    #pragma unroll
    for (int k = 0; k < SEG_LEN4 / THREADS; k++) {
        const int i = threadIdx.x + k * THREADS;
        float4 a = __ldcs(&x4[i]);
        float4 b = __ldcs(&y4[i]);
        sx  += a.x + a.y + a.z + a.w;
        sy  += b.x + b.y + b.z + b.w;
        sxx += a.x * a.x + a.y * a.y + a.z * a.z + a.w * a.w;
        syy += b.x * b.x + b.y * b.y + b.z * b.z + b.w * b.w;
        sxy += a.x * b.x + a.y * b.y + a.z * b.z + a.w * b.w;
    }

    // Warp reduce 5 values.
    #pragma unroll
    for (int o = 16; o > 0; o >>= 1) {
        sx  += __shfl_xor_sync(0xFFFFFFFFu, sx,  o);
        sy  += __shfl_xor_sync(0xFFFFFFFFu, sy,  o);
        sxx += __shfl_xor_sync(0xFFFFFFFFu, sxx, o);
        syy += __shfl_xor_sync(0xFFFFFFFFu, syy, o);
        sxy += __shfl_xor_sync(0xFFFFFFFFu, sxy, o);
    }

    __shared__ float sm[5][8];
    const int lane = threadIdx.x & 31;
    const int wid  = threadIdx.x >> 5;   // 8 warps
    if (lane == 0) {
        sm[0][wid] = sx; sm[1][wid] = sy; sm[2][wid] = sxx;
        sm[3][wid] = syy; sm[4][wid] = sxy;
    }
    __syncthreads();

    __shared__ int s_combine;
    if (wid == 0) {
        // Cross-warp reduce: lanes 0..7 hold warp partials.
        float v0 = (lane < 8) ? sm[0][lane] : 0.f;
        float v1 = (lane < 8) ? sm[1][lane] : 0.f;
        float v2 = (lane < 8) ? sm[2][lane] : 0.f;
        float v3 = (lane < 8) ? sm[3][lane] : 0.f;
        float v4 = (lane < 8) ? sm[4][lane] : 0.f;
        #pragma unroll
        for (int o = 4; o > 0; o >>= 1) {
            v0 += __shfl_xor_sync(0xFFFFFFFFu, v0, o);
            v1 += __shfl_xor_sync(0xFFFFFFFFu, v1, o);
            v2 += __shfl_xor_sync(0xFFFFFFFFu, v2, o);
            v3 += __shfl_xor_sync(0xFFFFFFFFu, v3, o);
            v4 += __shfl_xor_sync(0xFFFFFFFFu, v4, o);
        }
        if (lane == 0) {
            float* p = &g_part[(size_t)blockIdx.x * 5];
            p[0] = v0; p[1] = v1; p[2] = v2; p[3] = v3; p[4] = v4;
            __threadfence();
            unsigned int t = atomicAdd(&g_row_cnt[row], 1u);
            s_combine = (t == SEGS - 1) ? 1 : 0;
        }
        s_combine = __shfl_sync(0xFFFFFFFFu, s_combine, 0);

        // ---- This block finished the row: combine 8 segment partials. ----
        if (s_combine) {
            float c0 = 0.f, c1 = 0.f, c2 = 0.f, c3 = 0.f, c4 = 0.f;
            if (lane < SEGS) {
                const float* p = &g_part[((size_t)row * SEGS + lane) * 5];
                c0 = __ldcg(&p[0]); c1 = __ldcg(&p[1]); c2 = __ldcg(&p[2]);
                c3 = __ldcg(&p[3]); c4 = __ldcg(&p[4]);
            }
            #pragma unroll
            for (int o = 4; o > 0; o >>= 1) {   // fixed order -> deterministic
                c0 += __shfl_xor_sync(0xFFFFFFFFu, c0, o);
                c1 += __shfl_xor_sync(0xFFFFFFFFu, c1, o);
                c2 += __shfl_xor_sync(0xFFFFFFFFu, c2, o);
                c3 += __shfl_xor_sync(0xFFFFFFFFu, c3, o);
                c4 += __shfl_xor_sync(0xFFFFFFFFu, c4, o);
            }
            if (lane == 0) {
                const float n = (float)ROW_LEN;
                float mxx = c2 - c0 * c0 / n;
                float myy = c3 - c1 * c1 / n;
                float mxy = c4 - c0 * c1 / n;
                g_row_r[row]  = 1.0f - mxy * rsqrtf(fabsf(mxx * myy));
                g_row_cnt[row] = 0u;          // reset for next replay
                __threadfence();
                unsigned int t2 = atomicAdd(&g_done_rows, 1u);
                s_combine = (t2 == (unsigned int)(rows - 1)) ? 2 : 1;
            }
            s_combine = __shfl_sync(0xFFFFFFFFu, s_combine, 0);
        }
    }
    __syncthreads();   // broadcast s_combine to whole block

    // ---- Last row combined in THIS block: compute the mean (whole block). ----
    if (s_combine == 2) {
        float s = 0.f;
        for (int i = threadIdx.x; i < rows; i += THREADS)
            s += __ldcg(&g_row_r[i]);
        #pragma unroll
        for (int o = 16; o > 0; o >>= 1)
            s += __shfl_xor_sync(0xFFFFFFFFu, s, o);
        __shared__ float sm2[8];
        if (lane == 0) sm2[wid] = s;
        __syncthreads();
        if (wid == 0) {
            s = (lane < 8) ? sm2[lane] : 0.f;
            #pragma unroll
            for (int o = 4; o > 0; o >>= 1)
                s += __shfl_xor_sync(0xFFFFFFFFu, s, o);
            if (lane == 0) {
                out[0] = s / (float)rows;
                g_done_rows = 0u;             // reset for next replay
            }
        }
    }
}

extern "C" void kernel_launch(void* const* d_in, const int* in_sizes, int n_in,
                              void* d_out, int out_size) {
    const float* X = (const float*)d_in[0];
    const float* Y = (const float*)d_in[1];
    float* out = (float*)d_out;

    const int rows = in_sizes[0] / ROW_LEN;   // 768 for the given shape
    fused_loss_kernel<<<rows * SEGS, THREADS>>>(X, Y, out, rows);
}

// round 4
// speedup vs baseline: 1.1065x; 1.1065x over previous
#include <cuda_runtime.h>

// Problem: shape (8,16,6,256,256) -> rows = 768, row_len = 65536.
#define ROW_LEN    65536
#define SEGS       2                     // segments per row (tail-wave reduction)
#define SEG_LEN4   (ROW_LEN / SEGS / 4)  // 8192 float4
#define THREADS    1024                  // 8 float4 iterations per thread
#define MAX_ROWS   4096

// Device-global scratch (no allocations allowed). Counters reset in-kernel
// so graph replays see clean state.
__device__ float        g_part[MAX_ROWS * SEGS * 5];
__device__ unsigned int g_row_cnt[MAX_ROWS];
__device__ float        g_row_r[MAX_ROWS];
__device__ unsigned int g_done_rows = 0;

__global__ __launch_bounds__(THREADS, 1)
void fused_loss_kernel(const float* __restrict__ X, const float* __restrict__ Y,
                       float* __restrict__ out, int rows) {
    const int row = blockIdx.x >> 1;
    const int seg = blockIdx.x & 1;
    const size_t base4 = (size_t)row * (ROW_LEN / 4) + (size_t)seg * SEG_LEN4;
    const float4* __restrict__ x4 = reinterpret_cast<const float4*>(X) + base4;
    const float4* __restrict__ y4 = reinterpret_cast<const float4*>(Y) + base4;

    float sx = 0.f, sy = 0.f, sxx = 0.f, syy = 0.f, sxy = 0.f;

    // 8192 float4 / 1024 threads = 8 iterations; unroll 4 batches 8 LDG.128.
    #pragma unroll 4
    for (int i = threadIdx.x; i < SEG_LEN4; i += THREADS) {
        float4 a = __ldcs(&x4[i]);
        float4 b = __ldcs(&y4[i]);
        sx  += a.x + a.y + a.z + a.w;
        sy  += b.x + b.y + b.z + b.w;
        sxx += a.x * a.x + a.y * a.y + a.z * a.z + a.w * a.w;
        syy += b.x * b.x + b.y * b.y + b.z * b.z + b.w * b.w;
        sxy += a.x * b.x + a.y * b.y + a.z * b.z + a.w * b.w;
    }

    // Warp reduce 5 values.
    #pragma unroll
    for (int o = 16; o > 0; o >>= 1) {
        sx  += __shfl_xor_sync(0xFFFFFFFFu, sx,  o);
        sy  += __shfl_xor_sync(0xFFFFFFFFu, sy,  o);
        sxx += __shfl_xor_sync(0xFFFFFFFFu, sxx, o);
        syy += __shfl_xor_sync(0xFFFFFFFFu, syy, o);
        sxy += __shfl_xor_sync(0xFFFFFFFFu, sxy, o);
    }

    __shared__ float sm[5][32];
    const int lane = threadIdx.x & 31;
    const int wid  = threadIdx.x >> 5;   // 32 warps
    if (lane == 0) {
        sm[0][wid] = sx; sm[1][wid] = sy; sm[2][wid] = sxx;
        sm[3][wid] = syy; sm[4][wid] = sxy;
    }
    __syncthreads();

    __shared__ int s_state;
    if (wid == 0) {
        sx  = sm[0][lane];
        sy  = sm[1][lane];
        sxx = sm[2][lane];
        syy = sm[3][lane];
        sxy = sm[4][lane];
        #pragma unroll
        for (int o = 16; o > 0; o >>= 1) {
            sx  += __shfl_xor_sync(0xFFFFFFFFu, sx,  o);
            sy  += __shfl_xor_sync(0xFFFFFFFFu, sy,  o);
            sxx += __shfl_xor_sync(0xFFFFFFFFu, sxx, o);
            syy += __shfl_xor_sync(0xFFFFFFFFu, syy, o);
            sxy += __shfl_xor_sync(0xFFFFFFFFu, sxy, o);
        }
        if (lane == 0) {
            float* p = &g_part[(size_t)blockIdx.x * 5];
            p[0] = sx; p[1] = sy; p[2] = sxx; p[3] = syy; p[4] = sxy;
            __threadfence();
            unsigned int t = atomicAdd(&g_row_cnt[row], 1u);
            int state = 0;
            if (t == SEGS - 1) {
                // ---- Second segment done: combine both partials (fixed order). ----
                const float* p0 = &g_part[((size_t)row * SEGS + 0) * 5];
                const float* p1 = &g_part[((size_t)row * SEGS + 1) * 5];
                float c0 = __ldcg(&p0[0]) + __ldcg(&p1[0]);
                float c1 = __ldcg(&p0[1]) + __ldcg(&p1[1]);
                float c2 = __ldcg(&p0[2]) + __ldcg(&p1[2]);
                float c3 = __ldcg(&p0[3]) + __ldcg(&p1[3]);
                float c4 = __ldcg(&p0[4]) + __ldcg(&p1[4]);
                const float n = (float)ROW_LEN;
                float mxx = c2 - c0 * c0 / n;
                float myy = c3 - c1 * c1 / n;
                float mxy = c4 - c0 * c1 / n;
                g_row_r[row]   = 1.0f - mxy * rsqrtf(fabsf(mxx * myy));
                g_row_cnt[row] = 0u;           // reset for next replay
                __threadfence();
                unsigned int t2 = atomicAdd(&g_done_rows, 1u);
                state = (t2 == (unsigned int)(rows - 1)) ? 2 : 1;
            }
            s_state = state;
        }
    }
    __syncthreads();

    // ---- Last row combined in THIS block: compute the mean (whole block). ----
    if (s_state == 2) {
        float s = 0.f;
        for (int i = threadIdx.x; i < rows; i += THREADS)
            s += __ldcg(&g_row_r[i]);
        #pragma unroll
        for (int o = 16; o > 0; o >>= 1)
            s += __shfl_xor_sync(0xFFFFFFFFu, s, o);
        __shared__ float sm2[32];
        if (lane == 0) sm2[wid] = s;
        __syncthreads();
        if (wid == 0) {
            s = sm2[lane];
            #pragma unroll
            for (int o = 16; o > 0; o >>= 1)
                s += __shfl_xor_sync(0xFFFFFFFFu, s, o);
            if (lane == 0) {
                out[0] = s / (float)rows;
                g_done_rows = 0u;              // reset for next replay
            }
        }
    }
}

extern "C" void kernel_launch(void* const* d_in, const int* in_sizes, int n_in,
                              void* d_out, int out_size) {
    const float* X = (const float*)d_in[0];
    const float* Y = (const float*)d_in[1];
    float* out = (float*)d_out;

    const int rows = in_sizes[0] / ROW_LEN;   // 768 for the given shape
    fused_loss_kernel<<<rows * SEGS, THREADS>>>(X, Y, out, rows);
}

// round 5
// speedup vs baseline: 1.1285x; 1.0199x over previous
#include <cuda_runtime.h>

// Problem: shape (8,16,6,256,256) -> rows = 768, row_len = 65536.
#define ROW_LEN      65536
#define ROW_LEN4     (ROW_LEN / 4)        // 16384 float4 per row
#define CHUNK4       256                  // float4 per work unit
#define CHUNK_ITERS  (CHUNK4 / 32)        // 8 iterations per lane
#define CHUNKS_ROW   (ROW_LEN4 / CHUNK4)  // 64 chunks per row
#define THREADS      1024
#define MAX_ROWS     4096

// Device-global scratch (no allocations allowed). Counters reset in-kernel
// so graph replays see clean state.
__device__ float        g_part[(size_t)MAX_ROWS * CHUNKS_ROW * 5];
__device__ unsigned int g_row_cnt[MAX_ROWS];
__device__ float        g_row_r[MAX_ROWS];
__device__ unsigned int g_done_rows = 0;

__global__ __launch_bounds__(THREADS, 1)
void persistent_loss_kernel(const float* __restrict__ X, const float* __restrict__ Y,
                            float* __restrict__ out, int rows) {
    const float4* __restrict__ X4 = reinterpret_cast<const float4*>(X);
    const float4* __restrict__ Y4 = reinterpret_cast<const float4*>(Y);

    __shared__ unsigned int s_ticket;
    if (threadIdx.x == 0) s_ticket = 0u;
    __syncthreads();                      // the ONLY block barrier

    const int lane = threadIdx.x & 31;
    const unsigned int units_total = (unsigned int)rows * CHUNKS_ROW;

    // Static per-CTA unit range (imbalance <= 1 unit); dynamic per-warp inside.
    const unsigned int u0 = (unsigned int)(((unsigned long long)blockIdx.x * units_total) / gridDim.x);
    const unsigned int u1 = (unsigned int)(((unsigned long long)(blockIdx.x + 1) * units_total) / gridDim.x);
    const unsigned int count = u1 - u0;

    for (;;) {
        // ---- Warp grabs next work unit from the CTA-local ticket. ----
        unsigned int t;
        if (lane == 0) t = atomicAdd(&s_ticket, 1u);
        t = __shfl_sync(0xFFFFFFFFu, t, 0);
        if (t >= count) break;

        const unsigned int u    = u0 + t;
        const unsigned int row  = u / CHUNKS_ROW;
        const unsigned int chnk = u % CHUNKS_ROW;
        const size_t base4 = (size_t)row * ROW_LEN4 + (size_t)chnk * CHUNK4;
        const float4* __restrict__ x4 = X4 + base4;
        const float4* __restrict__ y4 = Y4 + base4;

        float sx = 0.f, sy = 0.f, sxx = 0.f, syy = 0.f, sxy = 0.f;
        #pragma unroll 4
        for (int it = 0; it < CHUNK_ITERS; it++) {
            const int i = (it << 5) + lane;
            float4 a = __ldcs(&x4[i]);
            float4 b = __ldcs(&y4[i]);
            sx  += a.x + a.y + a.z + a.w;
            sy  += b.x + b.y + b.z + b.w;
            sxx += a.x * a.x + a.y * a.y + a.z * a.z + a.w * a.w;
            syy += b.x * b.x + b.y * b.y + b.z * b.z + b.w * b.w;
            sxy += a.x * b.x + a.y * b.y + a.z * b.z + a.w * b.w;
        }

        // ---- Warp-level reduce (no barriers). ----
        #pragma unroll
        for (int o = 16; o > 0; o >>= 1) {
            sx  += __shfl_xor_sync(0xFFFFFFFFu, sx,  o);
            sy  += __shfl_xor_sync(0xFFFFFFFFu, sy,  o);
            sxx += __shfl_xor_sync(0xFFFFFFFFu, sxx, o);
            syy += __shfl_xor_sync(0xFFFFFFFFu, syy, o);
            sxy += __shfl_xor_sync(0xFFFFFFFFu, sxy, o);
        }

        int is_last = 0;
        if (lane == 0) {
            float* p = &g_part[(size_t)u * 5];
            p[0] = sx; p[1] = sy; p[2] = sxx; p[3] = syy; p[4] = sxy;
            __threadfence();
            unsigned int done = atomicAdd(&g_row_cnt[row], 1u);
            is_last = (done == CHUNKS_ROW - 1) ? 1 : 0;
        }
        is_last = __shfl_sync(0xFFFFFFFFu, is_last, 0);

        // ---- Last chunk of this row: combine 64 partials (fixed order). ----
        if (is_last) {
            const float* pb = &g_part[(size_t)row * CHUNKS_ROW * 5];
            float c0, c1, c2, c3, c4;
            {
                const float* pa = pb + (size_t)lane * 5;
                const float* pc = pb + (size_t)(lane + 32) * 5;
                c0 = __ldcg(&pa[0]) + __ldcg(&pc[0]);
                c1 = __ldcg(&pa[1]) + __ldcg(&pc[1]);
                c2 = __ldcg(&pa[2]) + __ldcg(&pc[2]);
                c3 = __ldcg(&pa[3]) + __ldcg(&pc[3]);
                c4 = __ldcg(&pa[4]) + __ldcg(&pc[4]);
            }
            #pragma unroll
            for (int o = 16; o > 0; o >>= 1) {    // fixed tree -> deterministic
                c0 += __shfl_xor_sync(0xFFFFFFFFu, c0, o);
                c1 += __shfl_xor_sync(0xFFFFFFFFu, c1, o);
                c2 += __shfl_xor_sync(0xFFFFFFFFu, c2, o);
                c3 += __shfl_xor_sync(0xFFFFFFFFu, c3, o);
                c4 += __shfl_xor_sync(0xFFFFFFFFu, c4, o);
            }
            int do_mean = 0;
            if (lane == 0) {
                const float n = (float)ROW_LEN;
                float mxx = c2 - c0 * c0 / n;
                float myy = c3 - c1 * c1 / n;
                float mxy = c4 - c0 * c1 / n;
                g_row_r[row]   = 1.0f - mxy * rsqrtf(fabsf(mxx * myy));
                g_row_cnt[row] = 0u;              // reset for next replay
                __threadfence();
                unsigned int t2 = atomicAdd(&g_done_rows, 1u);
                do_mean = (t2 == (unsigned int)(rows - 1)) ? 1 : 0;
            }
            do_mean = __shfl_sync(0xFFFFFFFFu, do_mean, 0);

            // ---- All rows done: this warp computes the final mean. ----
            if (do_mean) {
                float s = 0.f;
                for (int i = lane; i < rows; i += 32)
                    s += __ldcg(&g_row_r[i]);
                #pragma unroll
                for (int o = 16; o > 0; o >>= 1)
                    s += __shfl_xor_sync(0xFFFFFFFFu, s, o);
                if (lane == 0) {
                    out[0] = s / (float)rows;
                    g_done_rows = 0u;             // reset for next replay
                }
            }
        }
    }
}

extern "C" void kernel_launch(void* const* d_in, const int* in_sizes, int n_in,
                              void* d_out, int out_size) {
    const float* X = (const float*)d_in[0];
    const float* Y = (const float*)d_in[1];
    float* out = (float*)d_out;

    const int rows = in_sizes[0] / ROW_LEN;   // 768 for the given shape

    int num_sms = 148;
    cudaDeviceGetAttribute(&num_sms, cudaDevAttrMultiProcessorCount, 0);
    int grid = num_sms;                       // exactly one persistent CTA per SM
    if (grid > rows * CHUNKS_ROW) grid = rows * CHUNKS_ROW;

    persistent_loss_kernel<<<grid, THREADS>>>(X, Y, out, rows);
}

// round 6
// speedup vs baseline: 1.1389x; 1.0093x over previous
#include <cuda_runtime.h>

// Problem: shape (8,16,6,256,256) -> rows = 768, row_len = 65536.
#define ROW_LEN   65536
#define ROW_LEN4  (ROW_LEN / 4)
#define THREADS   1024
#define MAX_ROWS  4096

// Device-global scratch (no allocations allowed).
__device__ float        g_row_r[MAX_ROWS];
__device__ unsigned int g_done_count = 0;   // self-resetting; graph-replay safe

__global__ __launch_bounds__(THREADS, 1)
void fused_loss_kernel(const float* __restrict__ X, const float* __restrict__ Y,
                       float* __restrict__ out, int rows) {
    const size_t row = blockIdx.x;
    const float4* __restrict__ x4 = reinterpret_cast<const float4*>(X) + row * ROW_LEN4;
    const float4* __restrict__ y4 = reinterpret_cast<const float4*>(Y) + row * ROW_LEN4;

    float sx = 0.f, sy = 0.f, sxx = 0.f, syy = 0.f, sxy = 0.f;

    // 16384 float4 per row / 1024 threads = 16 iterations per thread.
    // __ldg (default-cached): R1 evidence says this streams ~8% faster than
    // __ldcs on this chip. unroll 8 -> 16 LDG.128 front-batched per thread.
    #pragma unroll 8
    for (int i = threadIdx.x; i < ROW_LEN4; i += THREADS) {
        float4 a = __ldg(&x4[i]);
        float4 b = __ldg(&y4[i]);
        sx  += a.x + a.y + a.z + a.w;
        sy  += b.x + b.y + b.z + b.w;
        sxx += a.x * a.x + a.y * a.y + a.z * a.z + a.w * a.w;
        syy += b.x * b.x + b.y * b.y + b.z * b.z + b.w * b.w;
        sxy += a.x * b.x + a.y * b.y + a.z * b.z + a.w * b.w;
    }

    // Warp reduce 5 values.
    #pragma unroll
    for (int o = 16; o > 0; o >>= 1) {
        sx  += __shfl_xor_sync(0xFFFFFFFFu, sx,  o);
        sy  += __shfl_xor_sync(0xFFFFFFFFu, sy,  o);
        sxx += __shfl_xor_sync(0xFFFFFFFFu, sxx, o);
        syy += __shfl_xor_sync(0xFFFFFFFFu, syy, o);
        sxy += __shfl_xor_sync(0xFFFFFFFFu, sxy, o);
    }

    __shared__ float sm[5][32];
    const int lane = threadIdx.x & 31;
    const int wid  = threadIdx.x >> 5;
    if (lane == 0) {
        sm[0][wid] = sx; sm[1][wid] = sy; sm[2][wid] = sxx;
        sm[3][wid] = syy; sm[4][wid] = sxy;
    }
    __syncthreads();

    if (wid == 0) {
        // 1024 threads -> exactly 32 warps; all slots valid.
        sx  = sm[0][lane];
        sy  = sm[1][lane];
        sxx = sm[2][lane];
        syy = sm[3][lane];
        sxy = sm[4][lane];
        #pragma unroll
        for (int o = 16; o > 0; o >>= 1) {
            sx  += __shfl_xor_sync(0xFFFFFFFFu, sx,  o);
            sy  += __shfl_xor_sync(0xFFFFFFFFu, sy,  o);
            sxx += __shfl_xor_sync(0xFFFFFFFFu, sxx, o);
            syy += __shfl_xor_sync(0xFFFFFFFFu, syy, o);
            sxy += __shfl_xor_sync(0xFFFFFFFFu, sxy, o);
        }
        if (lane == 0) {
            const float n = (float)ROW_LEN;
            float mxx = sxx - sx * sx / n;
            float myy = syy - sy * sy / n;
            float mxy = sxy - sx * sy / n;
            // r = 1 - Cov(x,y)/sqrt(|Var(x)Var(y)|)  (1/(n-1) cancels)
            g_row_r[row] = 1.0f - mxy * rsqrtf(fabsf(mxx * myy));
        }
    }

    // ---- Fused final mean: last CTA to finish reduces all per-row values. ----
    __shared__ unsigned int s_is_last;
    __syncthreads();
    if (threadIdx.x == 0) {
        __threadfence();  // make g_row_r[row] visible before the counter bump
        unsigned int t = atomicAdd(&g_done_count, 1u);
        s_is_last = (t == (unsigned int)(gridDim.x - 1)) ? 1u : 0u;
    }
    __syncthreads();

    if (s_is_last) {
        float s = 0.f;
        for (int i = threadIdx.x; i < rows; i += THREADS)
            s += __ldcg(&g_row_r[i]);
        #pragma unroll
        for (int o = 16; o > 0; o >>= 1)
            s += __shfl_xor_sync(0xFFFFFFFFu, s, o);
        __shared__ float sm2[32];
        if (lane == 0) sm2[wid] = s;
        __syncthreads();
        if (wid == 0) {
            s = sm2[lane];
            #pragma unroll
            for (int o = 16; o > 0; o >>= 1)
                s += __shfl_xor_sync(0xFFFFFFFFu, s, o);
            if (lane == 0) {
                out[0] = s / (float)rows;
                g_done_count = 0;   // reset for next graph replay
            }
        }
    }
}

extern "C" void kernel_launch(void* const* d_in, const int* in_sizes, int n_in,
                              void* d_out, int out_size) {
    const float* X = (const float*)d_in[0];
    const float* Y = (const float*)d_in[1];
    float* out = (float*)d_out;

    const int rows = in_sizes[0] / ROW_LEN;  // 768 for the given shape
    fused_loss_kernel<<<rows, THREADS>>>(X, Y, out, rows);
}

// round 7
// speedup vs baseline: 1.1663x; 1.0240x over previous
#include <cuda_runtime.h>

// Problem: shape (8,16,6,256,256) -> rows = 768, row_len = 65536.
#define ROW_LEN   65536
#define ROW_LEN4  (ROW_LEN / 4)
#define THREADS   512
#define MAX_ROWS  4096

// Device-global scratch (no allocations allowed).
__device__ float        g_row_r[MAX_ROWS];
__device__ unsigned int g_done_count = 0;   // self-resetting; graph-replay safe

// 128-bit non-coherent load with 256B L2 fetch-granularity hint.
__device__ __forceinline__ float4 ldg_nc_256(const float4* p) {
    float4 v;
    asm volatile("ld.global.nc.L2::256B.v4.f32 {%0,%1,%2,%3}, [%4];"
                 : "=f"(v.x), "=f"(v.y), "=f"(v.z), "=f"(v.w)
                 : "l"(p));
    return v;
}

__global__ __launch_bounds__(THREADS, 2)   // 2 resident CTAs/SM: overlap epilogue with next row's ramp
void fused_loss_kernel(const float* __restrict__ X, const float* __restrict__ Y,
                       float* __restrict__ out, int rows) {
    const size_t row = blockIdx.x;
    const float4* __restrict__ x4 = reinterpret_cast<const float4*>(X) + row * ROW_LEN4;
    const float4* __restrict__ y4 = reinterpret_cast<const float4*>(Y) + row * ROW_LEN4;

    float sx = 0.f, sy = 0.f, sxx = 0.f, syy = 0.f, sxy = 0.f;

    // 16384 float4 per row / 512 threads = 32 iterations; unroll 4 keeps
    // regs <= 64 (required for 2 CTAs/SM) with 8 LDG.128 batched per thread.
    #pragma unroll 4
    for (int i = threadIdx.x; i < ROW_LEN4; i += THREADS) {
        float4 a = ldg_nc_256(&x4[i]);
        float4 b = ldg_nc_256(&y4[i]);
        sx  += a.x + a.y + a.z + a.w;
        sy  += b.x + b.y + b.z + b.w;
        sxx += a.x * a.x + a.y * a.y + a.z * a.z + a.w * a.w;
        syy += b.x * b.x + b.y * b.y + b.z * b.z + b.w * b.w;
        sxy += a.x * b.x + a.y * b.y + a.z * b.z + a.w * b.w;
    }

    // Warp reduce 5 values.
    #pragma unroll
    for (int o = 16; o > 0; o >>= 1) {
        sx  += __shfl_xor_sync(0xFFFFFFFFu, sx,  o);
        sy  += __shfl_xor_sync(0xFFFFFFFFu, sy,  o);
        sxx += __shfl_xor_sync(0xFFFFFFFFu, sxx, o);
        syy += __shfl_xor_sync(0xFFFFFFFFu, syy, o);
        sxy += __shfl_xor_sync(0xFFFFFFFFu, sxy, o);
    }

    __shared__ float sm[5][16];
    const int lane = threadIdx.x & 31;
    const int wid  = threadIdx.x >> 5;   // 16 warps
    if (lane == 0) {
        sm[0][wid] = sx; sm[1][wid] = sy; sm[2][wid] = sxx;
        sm[3][wid] = syy; sm[4][wid] = sxy;
    }
    __syncthreads();

    if (wid == 0) {
        sx  = (lane < 16) ? sm[0][lane] : 0.f;
        sy  = (lane < 16) ? sm[1][lane] : 0.f;
        sxx = (lane < 16) ? sm[2][lane] : 0.f;
        syy = (lane < 16) ? sm[3][lane] : 0.f;
        sxy = (lane < 16) ? sm[4][lane] : 0.f;
        #pragma unroll
        for (int o = 8; o > 0; o >>= 1) {
            sx  += __shfl_xor_sync(0xFFFFFFFFu, sx,  o);
            sy  += __shfl_xor_sync(0xFFFFFFFFu, sy,  o);
            sxx += __shfl_xor_sync(0xFFFFFFFFu, sxx, o);
            syy += __shfl_xor_sync(0xFFFFFFFFu, syy, o);
            sxy += __shfl_xor_sync(0xFFFFFFFFu, sxy, o);
        }
        if (lane == 0) {
            const float n = (float)ROW_LEN;
            float mxx = sxx - sx * sx / n;
            float myy = syy - sy * sy / n;
            float mxy = sxy - sx * sy / n;
            // r = 1 - Cov(x,y)/sqrt(|Var(x)Var(y)|)  (1/(n-1) cancels)
            g_row_r[row] = 1.0f - mxy * rsqrtf(fabsf(mxx * myy));
        }
    }

    // ---- Fused final mean: last CTA to finish reduces all per-row values. ----
    __shared__ unsigned int s_is_last;
    __syncthreads();
    if (threadIdx.x == 0) {
        __threadfence();  // make g_row_r[row] visible before the counter bump
        unsigned int t = atomicAdd(&g_done_count, 1u);
        s_is_last = (t == (unsigned int)(gridDim.x - 1)) ? 1u : 0u;
    }
    __syncthreads();

    if (s_is_last) {
        float s = 0.f;
        for (int i = threadIdx.x; i < rows; i += THREADS)
            s += __ldcg(&g_row_r[i]);
        #pragma unroll
        for (int o = 16; o > 0; o >>= 1)
            s += __shfl_xor_sync(0xFFFFFFFFu, s, o);
        __shared__ float sm2[16];
        if (lane == 0) sm2[wid] = s;
        __syncthreads();
        if (wid == 0) {
            s = (lane < 16) ? sm2[lane] : 0.f;
            #pragma unroll
            for (int o = 8; o > 0; o >>= 1)
                s += __shfl_xor_sync(0xFFFFFFFFu, s, o);
            if (lane == 0) {
                out[0] = s / (float)rows;
                g_done_count = 0;   // reset for next graph replay
            }
        }
    }
}

extern "C" void kernel_launch(void* const* d_in, const int* in_sizes, int n_in,
                              void* d_out, int out_size) {
    const float* X = (const float*)d_in[0];
    const float* Y = (const float*)d_in[1];
    float* out = (float*)d_out;

    const int rows = in_sizes[0] / ROW_LEN;  // 768 for the given shape
    fused_loss_kernel<<<rows, THREADS>>>(X, Y, out, rows);
}